// round 10
// baseline (speedup 1.0000x reference)
#include <cuda_runtime.h>
#include <cstdint>
#include <cstddef>

// Problem constants
#define NU      100
#define TSTEPS  60
#define BTOT    8192
// output offsets (all float32, concatenated in reference tuple order)
static const size_t OFFU  = 0;         // u:        (B,60,7)
static const size_t OFFT  = 3440640;   // target:   (B,60)
static const size_t OFFRS = 3932160;   // respmask: (B,60)
static const size_t OFFL  = 4423680;   // licked:   (B,)
static const size_t OFFR  = 4431872;   // reward:   (B,)
static const size_t OFFZ  = 4440064;   // z_seq:    (B,60)
static const size_t OFFYF = 4931584;   // yf:       (B,100)

// noise_scale = 0.15 * sqrt(2*0.2)
#define NSCALE 0.09486832980505138f

// 4 trials per warp-PAIR (j-split: even warp j=0..49, odd warp j=50..99).
// 512 threads = 16 warps = 8 pairs = 32 trials/block; grid = 256.
#define TPP 4

typedef unsigned long long ull;

__device__ __forceinline__ void fma2(ull &a, ull x, ull y){
    asm("fma.rn.f32x2 %0, %1, %2, %0;" : "+l"(a) : "l"(x), "l"(y));
}
__device__ __forceinline__ void add2(ull &a, ull b){
    asm("add.rn.f32x2 %0, %0, %1;" : "+l"(a) : "l"(b));
}
__device__ __forceinline__ float2 unpk(ull v){
    float lo, hi;
    asm("mov.b64 {%0, %1}, %2;" : "=f"(lo), "=f"(hi) : "l"(v));
    return make_float2(lo, hi);
}

// Shared layout (floats):
//   Wpk [100][128] : Wpk[j*128 + 4l + k] = Wrec[(32k+l)][j]  (0 if unit>=100)
//                    -> lane reads 16B = native (wk0,wk1),(wk2,wk3) ull pairs
//   Ydup[100][68]  : per pair 8 floats [s0,s0,s1,s1,s2,s2,s3,s3] (duplicated)
//   WinS[7][128]   : |W_in_raw| transposed, 0 pad
//   EXA : acc exchange, 16 slots (pair,half) x 8 ull x 32 lanes = 8192 floats
//   EXL : logit partial exchange, 8 pairs x 2 halves x 4 floats
#define YS 68
#define SM_W    0
#define SM_Y    12800
#define SM_WIN  19600
#define SM_EXA  20496
#define SM_EXL  28688
#define SM_FLOATS 28752

__global__ __launch_bounds__(512, 1)
void rnn_dynrouting_kernel(
    const float* __restrict__ y0,      const float* __restrict__ noise,
    const int*   __restrict__ stimI,   const int*   __restrict__ rewI,
    const int*   __restrict__ instrI,
    const float* __restrict__ WinRaw,  const float* __restrict__ Wrec,
    const float* __restrict__ brec,    const float* __restrict__ wout,
    const float* __restrict__ bout,
    float* __restrict__ out)
{
    extern __shared__ float sm[];
    float* Wpk  = sm + SM_W;
    float* Yd   = sm + SM_Y;
    float* WinS = sm + SM_WIN;
    ull*   EXA  = reinterpret_cast<ull*>(sm + SM_EXA);
    float* EXL  = sm + SM_EXL;

    const int tid = threadIdx.x;
    const int bb  = blockIdx.x * 32;   // first trial of block

    // ---- one-time shared init ----
    for (int idx = tid; idx < 100*128; idx += 512) {
        int j = idx >> 7, c = idx & 127;
        int l = c >> 2, k = c & 3;
        int i = 32*k + l;
        Wpk[idx] = (i < NU) ? Wrec[i*NU + j] : 0.0f;
    }
    for (int idx = tid; idx < 7*128; idx += 512) {
        int k = idx >> 7, i = idx & 127;
        WinS[idx] = (i < NU) ? fabsf(WinRaw[i*7 + k]) : 0.0f;
    }
    for (int idx = tid; idx < 100*32; idx += 512) {
        int j = idx >> 5, c = idx & 31;
        int p = c >> 2, s = c & 3;
        float v = y0[(size_t)(bb + p*4 + s)*NU + j];
        Yd[j*YS + p*8 + 2*s]     = v;
        Yd[j*YS + p*8 + 2*s + 1] = v;
    }
    __syncthreads();

    const int lane = tid & 31;
    const int warp = tid >> 5;
    const int pair = warp >> 1;
    const int half = warp & 1;
    const int tb   = bb + pair*TPP;

    // row ownership: own(i) = (i<50) == (half==0); slot k covers unit 32k+lane
    bool own[4];
    own[0] = (half == 0);
    own[1] = (((32 + lane) < 50) == (half == 0));
    own[2] = (half == 1);
    own[3] = (half == 1) && (lane < 4);

    // per-lane constants
    float wo[4], bk[4];
    #pragma unroll
    for (int k = 0; k < 4; k++) {
        int i = 32*k + lane;
        bool valid = (i < NU);
        wo[k] = (own[k] && valid) ? wout[i] : 0.0f;
        bk[k] = valid ? brec[i] : 0.0f;
    }
    const float b0 = bout[0];

    // per-trial constants (bit-packed, replicated in both warps of the pair)
    unsigned isRewM = 0, instrBM = 0, stimP = 0;
    #pragma unroll
    for (int s = 0; s < TPP; s++) {
        int b = tb + s;
        int sv = stimI[b];
        stimP  |= (unsigned)(sv & 3) << (2*s);
        isRewM |= (unsigned)(sv == rewI[b]) << s;
        instrBM|= (unsigned)(instrI[b] > 0) << s;
    }

    // per-trial state (replicated)
    unsigned lickedM = 0, instrFiredM = 0;
    int lickT[TPP];
    #pragma unroll
    for (int s = 0; s < TPP; s++) lickT[s] = TSTEPS + 1;

    // y state (kept in regs; garbage ok for unowned slots: gated by wo/publish)
    float y[4][TPP];
    #pragma unroll
    for (int k = 0; k < 4; k++) {
        int i = 32*k + lane;
        #pragma unroll
        for (int s = 0; s < TPP; s++)
            y[k][s] = (i < NU) ? y0[(size_t)(tb + s)*NU + i] : 0.0f;
    }

    const float* wp  = Wpk + 4*lane;
    const float* yrd = Yd + pair*8;
    const int    j0  = half*50;
    const float* nb  = noise + (size_t)tb*(TSTEPS*NU) + lane;
    ull*   myx = EXA + (size_t)(pair*2 + half)*256;
    ull*   pxx = EXA + (size_t)(pair*2 + (half ^ 1))*256;
    float* myl = EXL + pair*8 + half*4;
    const float* lgp = EXL + pair*8;

    // ==================== time loop ====================
    for (int t = 0; t < TSTEPS; t++) {
        const bool inResp = (t >= 20) && (t < 35);
        const bool inStim = (t >= 10) && (t < 15);

        // ---- per-trial coefficients (replicated) ----
        float cA[TPP], cB[TPP];
        unsigned instrActM = 0;
        #pragma unroll
        for (int s = 0; s < TPP; s++) {
            bool lic = (lickedM >> s) & 1;
            bool ifd = (instrFiredM >> s) & 1;
            bool irw = (isRewM >> s) & 1;
            bool ib  = (instrBM >> s) & 1;
            bool delivered = ifd || (lic && irw);
            if (ib && !delivered && (t == 30)) instrFiredM |= 1u << s;
            bool instrAct = ((instrFiredM >> s) & 1) && (t >= 30) && (t < 35);
            if (instrAct) instrActM |= 1u << s;
            bool lickDyn = lic && (t > lickT[s]) && (t < lickT[s] + 5);
            cA[s] = (instrAct ? 1.0f : 0.0f) + ((lickDyn && irw) ? 1.0f : 0.0f);
            cB[s] = lickDyn ? 1.0f : 0.0f;
        }

        // ---- prefetch noise for OWNED units only (no duplication) ----
        float nz[4][TPP];
        #pragma unroll
        for (int s = 0; s < TPP; s++) {
            const float* p = nb + (size_t)s*(TSTEPS*NU);
            nz[0][s] = own[0] ? __ldg(p)      : 0.0f;
            nz[1][s] = own[1] ? __ldg(p + 32) : 0.0f;
            nz[2][s] = own[2] ? __ldg(p + 64) : 0.0f;
            nz[3][s] = own[3] ? __ldg(p + 96) : 0.0f;
        }
        nb += NU;

        // ---- matvec over own j-half: 2 unit-pairs x 4 trials, MOV-free ----
        ull acc[2][TPP];
        #pragma unroll
        for (int s = 0; s < TPP; s++) { acc[0][s] = 0ull; acc[1][s] = 0ull; }
        #pragma unroll 5
        for (int j = j0; j < j0 + 50; j++) {
            ulonglong2 w2 = *reinterpret_cast<const ulonglong2*>(wp + j*128); // (wk0,wk1),(wk2,wk3)
            const float* yj = yrd + j*YS;
            ulonglong2 ya = *reinterpret_cast<const ulonglong2*>(yj);      // (s0,s0),(s1,s1)
            ulonglong2 yb = *reinterpret_cast<const ulonglong2*>(yj + 4);  // (s2,s2),(s3,s3)
            fma2(acc[0][0], w2.x, ya.x); fma2(acc[0][1], w2.x, ya.y);
            fma2(acc[0][2], w2.x, yb.x); fma2(acc[0][3], w2.x, yb.y);
            fma2(acc[1][0], w2.y, ya.x); fma2(acc[1][1], w2.y, ya.y);
            fma2(acc[1][2], w2.y, yb.x); fma2(acc[1][3], w2.y, yb.y);
        }

        // ---- exchange partial sums with co-warp ----
        #pragma unroll
        for (int p = 0; p < 2; p++)
            #pragma unroll
            for (int s = 0; s < TPP; s++)
                myx[(p*4 + s)*32 + lane] = acc[p][s];
        asm volatile("bar.sync %0, %1;" :: "r"(pair + 1), "r"(64) : "memory");
        #pragma unroll
        for (int p = 0; p < 2; p++)
            #pragma unroll
            for (int s = 0; s < TPP; s++)
                add2(acc[p][s], pxx[(p*4 + s)*32 + lane]);

        // ---- epilogue ----
        const float a6 = inResp ? 1.0f : 0.0f;
        const bool doAdd = (t >= 20);
        #pragma unroll
        for (int p = 0; p < 2; p++) {
            const int k0 = 2*p, k1 = 2*p + 1;
            const float w6a = WinS[6*128 + 32*k0 + lane], w6b = WinS[6*128 + 32*k1 + lane];
            const float w4a = WinS[4*128 + 32*k0 + lane], w4b = WinS[4*128 + 32*k1 + lane];
            const float w5a = WinS[5*128 + 32*k0 + lane], w5b = WinS[5*128 + 32*k1 + lane];
            #pragma unroll
            for (int s = 0; s < TPP; s++) {
                float2 v = unpk(acc[p][s]);
                float pa = v.x + bk[k0];
                float pb = v.y + bk[k1];
                if (inStim) {
                    int sv = (stimP >> (2*s)) & 3;
                    pa += WinS[sv*128 + 32*k0 + lane];
                    pb += WinS[sv*128 + 32*k1 + lane];
                }
                pa = fmaf(a6, w6a, pa);
                pb = fmaf(a6, w6b, pb);
                if (doAdd) {
                    pa = fmaf(cA[s], w4a, fmaf(cB[s], w5a, pa));
                    pb = fmaf(cA[s], w4b, fmaf(cB[s], w5b, pb));
                }
                pa = fmaf(NSCALE, nz[k0][s], pa);
                pb = fmaf(NSCALE, nz[k1][s], pb);
                y[k0][s] = 0.8f * y[k0][s] + 0.2f * fmaxf(pa, 0.0f);
                y[k1][s] = 0.8f * y[k1][s] + 0.2f * fmaxf(pb, 0.0f);
            }
        }

        // ---- publish owned rows (duplicated; rows are warp-private) ----
        #pragma unroll
        for (int k = 0; k < 4; k++) {
            if (own[k]) {
                float* row = Yd + (size_t)(32*k + lane)*YS + pair*8;
                *reinterpret_cast<float4*>(row)     = make_float4(y[k][0], y[k][0], y[k][1], y[k][1]);
                *reinterpret_cast<float4*>(row + 4) = make_float4(y[k][2], y[k][2], y[k][3], y[k][3]);
            }
        }

        // ---- readout: own-half partial logits, butterfly, exchange ----
        float part[TPP];
        #pragma unroll
        for (int s = 0; s < TPP; s++)
            part[s] = fmaf(y[0][s], wo[0],
                      fmaf(y[1][s], wo[1],
                      fmaf(y[2][s], wo[2], y[3][s] * wo[3])));
        #pragma unroll
        for (int off = 16; off > 0; off >>= 1) {
            #pragma unroll
            for (int s = 0; s < TPP; s++)
                part[s] += __shfl_xor_sync(0xffffffffu, part[s], off);
        }
        float myP = part[0];
        if (lane == 1) myP = part[1];
        if (lane == 2) myP = part[2];
        if (lane == 3) myP = part[3];
        if (lane < TPP) myl[lane] = myP;
        asm volatile("bar.sync %0, %1;" :: "r"(pair + 1), "r"(64) : "memory");
        float4 lA = *reinterpret_cast<const float4*>(lgp);
        float4 lB = *reinterpret_cast<const float4*>(lgp + 4);
        float lg[TPP];
        lg[0] = lA.x + lB.x + b0; lg[1] = lA.y + lB.y + b0;
        lg[2] = lA.z + lB.z + b0; lg[3] = lA.w + lB.w + b0;

        // ---- lick state machine (replicated, bit-identical inputs) ----
        unsigned u5M = 0, u4M = 0;
        #pragma unroll
        for (int s = 0; s < TPP; s++) {
            bool lic = (lickedM >> s) & 1;
            bool trig = inResp && !lic && (lg[s] > 0.0f);   // sigmoid(x)>0.5 <=> x>0
            if (trig) { lickT[s] = t; lickedM |= 1u << s; }
            bool lic2 = (lickedM >> s) & 1;
            bool u5 = lic2 && (t >= lickT[s]) && (t < lickT[s] + 5);
            bool u4 = ((instrActM >> s) & 1) || (u5 && ((isRewM >> s) & 1));
            if (u5) u5M |= 1u << s;
            if (u4) u4M |= 1u << s;
        }
        if (half == 0 && lane < TPP) {
            int s = lane;
            float lgs = lg[0];
            if (s == 1) lgs = lg[1];
            if (s == 2) lgs = lg[2];
            if (s == 3) lgs = lg[3];
            out[OFFZ + (size_t)(tb + s)*TSTEPS + t] = 1.0f / (1.0f + __expf(-lgs));
            size_t ub = OFFU + (size_t)(tb + s)*(TSTEPS*7) + (size_t)t*7;
            out[ub + 4] = ((u4M >> s) & 1) ? 1.0f : 0.0f;
            out[ub + 5] = ((u5M >> s) & 1) ? 1.0f : 0.0f;
        }
    }

    // ==================== final outputs ====================
    // yf: each warp writes its OWNED units (full coverage across the pair)
    #pragma unroll
    for (int k = 0; k < 4; k++) {
        if (own[k]) {
            #pragma unroll
            for (int s = 0; s < TPP; s++)
                out[OFFYF + (size_t)(tb + s)*NU + 32*k + lane] = y[k][s];
        }
    }
    if (half == 0) {
        // licked / reward_delivered
        if (lane < TPP) {
            int s = lane;
            bool lic = (lickedM >> s) & 1;
            bool irw = (isRewM >> s) & 1;
            bool ifd = (instrFiredM >> s) & 1;
            out[OFFL + (size_t)(tb + s)] = lic ? 1.0f : 0.0f;
            out[OFFR + (size_t)(tb + s)] = (ifd || (lic && irw)) ? 1.0f : 0.0f;
        }
        // static per-(trial,t) outputs
        for (int idx = lane; idx < TPP*TSTEPS; idx += 32) {
            int s = idx / TSTEPS;
            int t = idx - s*TSTEPS;
            size_t b = (size_t)(tb + s);
            bool resp = (t >= 20) && (t < 35);
            bool stm  = (t >= 10) && (t < 15);
            int sv = (stimP >> (2*s)) & 3;
            bool irw = (isRewM >> s) & 1;
            float* ub = out + OFFU + b*(TSTEPS*7) + (size_t)t*7;
            ub[0] = (stm && sv == 0) ? 1.0f : 0.0f;
            ub[1] = (stm && sv == 1) ? 1.0f : 0.0f;
            ub[2] = (stm && sv == 2) ? 1.0f : 0.0f;
            ub[3] = (stm && sv == 3) ? 1.0f : 0.0f;
            ub[6] = resp ? 1.0f : 0.0f;
            out[OFFT  + b*TSTEPS + t] = (irw && resp) ? 1.0f : 0.0f;
            out[OFFRS + b*TSTEPS + t] = resp ? 1.0f : 0.0f;
        }
    }
}

extern "C" void kernel_launch(void* const* d_in, const int* in_sizes, int n_in,
                              void* d_out, int out_size) {
    const float* y0     = (const float*)d_in[0];
    const float* noise  = (const float*)d_in[1];
    const int*   stim   = (const int*)  d_in[2];
    const int*   rew    = (const int*)  d_in[3];
    const int*   instr  = (const int*)  d_in[4];
    const float* WinRaw = (const float*)d_in[5];
    const float* Wrec   = (const float*)d_in[6];
    const float* brec   = (const float*)d_in[7];
    const float* wout   = (const float*)d_in[8];
    const float* bout   = (const float*)d_in[9];
    float* out = (float*)d_out;

    const int smem_bytes = SM_FLOATS * (int)sizeof(float);  // ~115 KB
    cudaFuncSetAttribute(rnn_dynrouting_kernel,
                         cudaFuncAttributeMaxDynamicSharedMemorySize, smem_bytes);
    rnn_dynrouting_kernel<<<BTOT/32, 512, smem_bytes>>>(
        y0, noise, stim, rew, instr, WinRaw, Wrec, brec, wout, bout, out);
}

// round 11
// speedup vs baseline: 1.3695x; 1.3695x over previous
#include <cuda_runtime.h>
#include <cstdint>
#include <cstddef>

// Problem constants
#define NU      100
#define TSTEPS  60
#define BTOT    8192
// output offsets (all float32, concatenated in reference tuple order)
static const size_t OFFU  = 0;         // u:        (B,60,7)
static const size_t OFFT  = 3440640;   // target:   (B,60)
static const size_t OFFRS = 3932160;   // respmask: (B,60)
static const size_t OFFL  = 4423680;   // licked:   (B,)
static const size_t OFFR  = 4431872;   // reward:   (B,)
static const size_t OFFZ  = 4440064;   // z_seq:    (B,60)
static const size_t OFFYF = 4931584;   // yf:       (B,100)

// noise_scale = 0.15 * sqrt(2*0.2)
#define NSCALE 0.09486832980505138f

// 8 trials/warp, 8 warps (256 thr)/block = 64 trials/block, grid 128.
#define TPW 8

typedef unsigned long long ull;

__device__ __forceinline__ void fma2(ull &a, ull x, ull y){
    asm("fma.rn.f32x2 %0, %1, %2, %0;" : "+l"(a) : "l"(x), "l"(y));
}
__device__ __forceinline__ ull dup2(float x){
    ull r;
    asm("mov.b64 %0, {%1, %1};" : "=l"(r) : "f"(x));
    return r;
}
__device__ __forceinline__ float2 unpk(ull v){
    float lo, hi;
    asm("mov.b64 {%0, %1}, %2;" : "=f"(lo), "=f"(hi) : "l"(v));
    return make_float2(lo, hi);
}

// Shared layout (floats):
//   W1 [100][128] : W1[j*128+4l+{0,1}] = dup W[l][j];      +{2,3} = dup W[32+l][j]
//   W2 [100][128] : W2[j*128+4l+{0,1}] = dup W[64+l][j];   +{2,3} = dup W[96+l][j] (0 pad)
//     -> lane reads 16B from each: ready-made (w,w) f32x2 operands, ZERO MOVs.
//     -> bank-check: lanes 0-7 word addr 4l mod 32 = {0,4,...,28} distinct: conflict-free.
//   Ybuf[2][100][68] : double-buffered y, trial-packed 8 floats per warp per row
//   WinS[7][128]  : WinS[k*128 + i] = |W_in_raw[i][k]|  (0 pad)
#define YS 68
#define SM_W1  0
#define SM_W2  12800
#define SM_Y   25600
#define YBUFSZ 6800
#define SM_WIN (25600 + 2*YBUFSZ)
#define SM_FLOATS (25600 + 2*YBUFSZ + 7*128)

__global__ __launch_bounds__(256, 1)
void rnn_dynrouting_kernel(
    const float* __restrict__ y0,      const float* __restrict__ noise,
    const int*   __restrict__ stimI,   const int*   __restrict__ rewI,
    const int*   __restrict__ instrI,
    const float* __restrict__ WinRaw,  const float* __restrict__ Wrec,
    const float* __restrict__ brec,    const float* __restrict__ wout,
    const float* __restrict__ bout,
    float* __restrict__ out)
{
    extern __shared__ float sm[];
    float* W1   = sm + SM_W1;
    float* W2   = sm + SM_W2;
    float* Ybuf = sm + SM_Y;
    float* WinS = sm + SM_WIN;

    const int tid = threadIdx.x;

    // ---- one-time shared init ----
    for (int idx = tid; idx < 100*128; idx += 256) {
        int j = idx >> 7, c = idx & 127;
        int l = c >> 2, q = c & 3;
        int k = q >> 1;                          // which unit of the pair
        // W1: units 32*k + l (k=0,1); W2: units 32*(2+k) + l (k=0,1)
        W1[idx] = Wrec[(32*k + l)*NU + j];
        int i2 = 32*(2 + k) + l;
        W2[idx] = (i2 < NU) ? Wrec[i2*NU + j] : 0.0f;
    }
    for (int idx = tid; idx < 7*128; idx += 256) {
        int k = idx >> 7, i = idx & 127;
        WinS[idx] = (i < NU) ? fabsf(WinRaw[i*7 + k]) : 0.0f;
    }
    __syncthreads();

    const int lane = tid & 31;
    const int warp = tid >> 5;
    const int tb   = blockIdx.x * 64 + warp * TPW;   // first trial of this warp
    // interleaved unit ownership: unit(u) = 32u + lane
    const bool v3  = (lane < 4);                     // u==3 validity

    // per-lane constants (4 units)
    float w4[4], w5[4], w6[4], wo[4];
    ull bd[4];
    #pragma unroll
    for (int u = 0; u < 4; u++) {
        int i = 32*u + lane;
        bool v = (u < 3) || v3;
        w4[u] = WinS[4*128 + i];
        w5[u] = WinS[5*128 + i];
        w6[u] = WinS[6*128 + i];
        wo[u] = v ? wout[i] : 0.0f;
        bd[u] = dup2(v ? brec[i] : 0.0f);
    }
    const float b0 = bout[0];

    // per-trial constants, replicated in every lane (bit-packed)
    unsigned isRewM = 0, instrBM = 0, stimP = 0;
    #pragma unroll
    for (int s = 0; s < TPW; s++) {
        int b = tb + s;
        int sv = stimI[b];
        stimP  |= (unsigned)(sv & 3) << (2*s);
        isRewM |= (unsigned)(sv == rewI[b]) << s;
        instrBM|= (unsigned)(instrI[b] > 0) << s;
    }

    // per-trial state (replicated)
    unsigned lickedM = 0, instrFiredM = 0;
    int lickT[TPW];
    #pragma unroll
    for (int s = 0; s < TPW; s++) lickT[s] = TSTEPS + 1;

    // y state: y[u][s]
    float y[4][TPW];
    #pragma unroll
    for (int u = 0; u < 4; u++) {
        bool v = (u < 3) || v3;
        #pragma unroll
        for (int s = 0; s < TPW; s++)
            y[u][s] = v ? y0[(size_t)(tb + s)*NU + 32*u + lane] : 0.0f;
    }
    // publish initial y into buffer 0 (conflict-free: lane stride 68 = 4 mod 32)
    #pragma unroll
    for (int u = 0; u < 4; u++) {
        if (u < 3 || v3) {
            float* row = Ybuf + (size_t)(32*u + lane)*YS + TPW*warp;
            *reinterpret_cast<float4*>(row)     = make_float4(y[u][0], y[u][1], y[u][2], y[u][3]);
            *reinterpret_cast<float4*>(row + 4) = make_float4(y[u][4], y[u][5], y[u][6], y[u][7]);
        }
    }
    __syncwarp();

    const float* wp1 = W1 + 4*lane;
    const float* wp2 = W2 + 4*lane;
    const float* nb  = noise + (size_t)tb*(TSTEPS*NU) + lane;
    int cur = 0;

    float nz[4][TPW];

    // ==================== time loop ====================
    for (int t = 0; t < TSTEPS; t++) {
        const bool inResp = (t >= 20) && (t < 35);
        const bool inStim = (t >= 10) && (t < 15);
        const float* yp = Ybuf + cur*YBUFSZ + TPW*warp;
        float*      pub = Ybuf + (cur ^ 1)*YBUFSZ;

        // ---- prefetch noise first (max MLP; hidden under matvec) ----
        #pragma unroll
        for (int s = 0; s < TPW; s++) {
            const float* p = nb + (size_t)s*(TSTEPS*NU);
            nz[0][s] = __ldg(p);
            nz[1][s] = __ldg(p + 32);
            nz[2][s] = __ldg(p + 64);
            nz[3][s] = v3 ? __ldg(p + 96) : 0.0f;
        }
        nb += NU;

        // ---- per-trial coefficients (replicated in all lanes) ----
        float cA[TPW], cB[TPW];
        unsigned instrActM = 0;
        #pragma unroll
        for (int s = 0; s < TPW; s++) {
            bool lic = (lickedM >> s) & 1;
            bool ifd = (instrFiredM >> s) & 1;
            bool irw = (isRewM >> s) & 1;
            bool ib  = (instrBM >> s) & 1;
            bool delivered = ifd || (lic && irw);
            if (ib && !delivered && (t == 30)) instrFiredM |= 1u << s;
            bool instrAct = ((instrFiredM >> s) & 1) && (t >= 30) && (t < 35);
            if (instrAct) instrActM |= 1u << s;
            bool lickDyn = lic && (t > lickT[s]) && (t < lickT[s] + 5);
            cA[s] = (instrAct ? 1.0f : 0.0f) + ((lickDyn && irw) ? 1.0f : 0.0f);
            cB[s] = lickDyn ? 1.0f : 0.0f;
        }

        // ---- matvec: 20 issues/j, ZERO MOVs (W pre-duplicated in shared) ----
        ull acc[4][4];
        #pragma unroll
        for (int u = 0; u < 4; u++) {
            acc[u][0] = bd[u]; acc[u][1] = bd[u]; acc[u][2] = bd[u]; acc[u][3] = bd[u];
        }
        #pragma unroll 10
        for (int j = 0; j < NU; j++) {
            ulonglong2 q1 = *reinterpret_cast<const ulonglong2*>(wp1 + j*128); // (w0,w0),(w1,w1)
            ulonglong2 q2 = *reinterpret_cast<const ulonglong2*>(wp2 + j*128); // (w2,w2),(w3,w3)
            ulonglong2 ya = *reinterpret_cast<const ulonglong2*>(yp + j*YS);     // trials 0-3
            ulonglong2 yb = *reinterpret_cast<const ulonglong2*>(yp + j*YS + 4); // trials 4-7
            // grouped by shared y operand (reuse-friendly)
            fma2(acc[0][0], q1.x, ya.x); fma2(acc[1][0], q1.y, ya.x); fma2(acc[2][0], q2.x, ya.x); fma2(acc[3][0], q2.y, ya.x);
            fma2(acc[0][1], q1.x, ya.y); fma2(acc[1][1], q1.y, ya.y); fma2(acc[2][1], q2.x, ya.y); fma2(acc[3][1], q2.y, ya.y);
            fma2(acc[0][2], q1.x, yb.x); fma2(acc[1][2], q1.y, yb.x); fma2(acc[2][2], q2.x, yb.x); fma2(acc[3][2], q2.y, yb.x);
            fma2(acc[0][3], q1.x, yb.y); fma2(acc[1][3], q1.y, yb.y); fma2(acc[2][3], q2.x, yb.y); fma2(acc[3][3], q2.y, yb.y);
        }

        // ---- epilogue: pre -> relu -> leaky update ----
        const float a6 = inResp ? 1.0f : 0.0f;
        const bool doAdd = (t >= 20);   // cA/cB only nonzero from t>=21/30
        #pragma unroll
        for (int u = 0; u < 4; u++) {
            #pragma unroll
            for (int p = 0; p < 4; p++) {
                float2 v = unpk(acc[u][p]);
                int s0 = 2*p, s1 = 2*p + 1;
                float pa = v.x, pb = v.y;
                if (inStim) {
                    pa += WinS[((stimP >> (2*s0)) & 3)*128 + 32*u + lane];
                    pb += WinS[((stimP >> (2*s1)) & 3)*128 + 32*u + lane];
                }
                pa = fmaf(a6, w6[u], pa);
                pb = fmaf(a6, w6[u], pb);
                if (doAdd) {
                    pa = fmaf(cA[s0], w4[u], fmaf(cB[s0], w5[u], pa));
                    pb = fmaf(cA[s1], w4[u], fmaf(cB[s1], w5[u], pb));
                }
                pa = fmaf(NSCALE, nz[u][s0], pa);
                pb = fmaf(NSCALE, nz[u][s1], pb);
                y[u][s0] = 0.8f * y[u][s0] + 0.2f * fmaxf(pa, 0.0f);
                y[u][s1] = 0.8f * y[u][s1] + 0.2f * fmaxf(pb, 0.0f);
            }
        }

        // ---- publish y to the OTHER buffer (no pre-sync needed) ----
        #pragma unroll
        for (int u = 0; u < 4; u++) {
            if (u < 3 || v3) {
                float* row = pub + (size_t)(32*u + lane)*YS + TPW*warp;
                *reinterpret_cast<float4*>(row)     = make_float4(y[u][0], y[u][1], y[u][2], y[u][3]);
                *reinterpret_cast<float4*>(row + 4) = make_float4(y[u][4], y[u][5], y[u][6], y[u][7]);
            }
        }
        __syncwarp();   // publish visible to co-lanes before next step's matvec

        // ---- readout: logit[s] = y . w_out + b0 via shuffle butterfly ----
        float part[TPW];
        #pragma unroll
        for (int s = 0; s < TPW; s++) {
            part[s] = fmaf(y[0][s], wo[0],
                      fmaf(y[1][s], wo[1],
                      fmaf(y[2][s], wo[2], y[3][s] * wo[3])));
        }
        #pragma unroll
        for (int off = 16; off > 0; off >>= 1) {
            #pragma unroll
            for (int s = 0; s < TPW; s++)
                part[s] += __shfl_xor_sync(0xffffffffu, part[s], off);
        }

        // ---- lick state machine + per-step outputs ----
        unsigned u5M = 0, u4M = 0;
        #pragma unroll
        for (int s = 0; s < TPW; s++) {
            float lg = part[s] + b0;
            bool lic = (lickedM >> s) & 1;
            bool trig = inResp && !lic && (lg > 0.0f);   // sigmoid(x)>0.5 <=> x>0
            if (trig) { lickT[s] = t; lickedM |= 1u << s; }
            bool lic2 = (lickedM >> s) & 1;
            bool u5 = lic2 && (t >= lickT[s]) && (t < lickT[s] + 5);
            bool u4 = ((instrActM >> s) & 1) || (u5 && ((isRewM >> s) & 1));
            if (u5) u5M |= 1u << s;
            if (u4) u4M |= 1u << s;
        }
        // lane s (<8) writes trial s's z, u[...,4], u[...,5]
        float myPart = part[0];
        #pragma unroll
        for (int s = 1; s < TPW; s++) if ((lane & 7) == s) myPart = part[s];
        if (lane < TPW) {
            int s = lane;
            float lg = myPart + b0;
            out[OFFZ + (size_t)(tb + s)*TSTEPS + t] = 1.0f / (1.0f + __expf(-lg));
            size_t ub = OFFU + (size_t)(tb + s)*(TSTEPS*7) + (size_t)t*7;
            out[ub + 4] = ((u4M >> s) & 1) ? 1.0f : 0.0f;
            out[ub + 5] = ((u5M >> s) & 1) ? 1.0f : 0.0f;
        }
        cur ^= 1;
    }

    // ==================== final outputs ====================
    // yf (coalesced scalar stores)
    #pragma unroll
    for (int u = 0; u < 4; u++) {
        if (u < 3 || v3) {
            #pragma unroll
            for (int s = 0; s < TPW; s++)
                out[OFFYF + (size_t)(tb + s)*NU + 32*u + lane] = y[u][s];
        }
    }
    // licked / reward_delivered
    if (lane < TPW) {
        int s = lane;
        bool lic = (lickedM >> s) & 1;
        bool irw = (isRewM >> s) & 1;
        bool ifd = (instrFiredM >> s) & 1;
        out[OFFL + (size_t)(tb + s)] = lic ? 1.0f : 0.0f;
        out[OFFR + (size_t)(tb + s)] = (ifd || (lic && irw)) ? 1.0f : 0.0f;
    }
    // static per-(trial,t) outputs
    for (int idx = lane; idx < TPW*TSTEPS; idx += 32) {
        int s = idx / TSTEPS;
        int t = idx - s*TSTEPS;
        size_t b = (size_t)(tb + s);
        bool resp = (t >= 20) && (t < 35);
        bool stm  = (t >= 10) && (t < 15);
        int sv = (stimP >> (2*s)) & 3;
        bool irw = (isRewM >> s) & 1;
        float* ub = out + OFFU + b*(TSTEPS*7) + (size_t)t*7;
        ub[0] = (stm && sv == 0) ? 1.0f : 0.0f;
        ub[1] = (stm && sv == 1) ? 1.0f : 0.0f;
        ub[2] = (stm && sv == 2) ? 1.0f : 0.0f;
        ub[3] = (stm && sv == 3) ? 1.0f : 0.0f;
        ub[6] = resp ? 1.0f : 0.0f;
        out[OFFT  + b*TSTEPS + t] = (irw && resp) ? 1.0f : 0.0f;
        out[OFFRS + b*TSTEPS + t] = resp ? 1.0f : 0.0f;
    }
}

extern "C" void kernel_launch(void* const* d_in, const int* in_sizes, int n_in,
                              void* d_out, int out_size) {
    const float* y0     = (const float*)d_in[0];
    const float* noise  = (const float*)d_in[1];
    const int*   stim   = (const int*)  d_in[2];
    const int*   rew    = (const int*)  d_in[3];
    const int*   instr  = (const int*)  d_in[4];
    const float* WinRaw = (const float*)d_in[5];
    const float* Wrec   = (const float*)d_in[6];
    const float* brec   = (const float*)d_in[7];
    const float* wout   = (const float*)d_in[8];
    const float* bout   = (const float*)d_in[9];
    float* out = (float*)d_out;

    const int smem_bytes = SM_FLOATS * (int)sizeof(float);  // ~160.4 KB (1 block/SM)
    cudaFuncSetAttribute(rnn_dynrouting_kernel,
                         cudaFuncAttributeMaxDynamicSharedMemorySize, smem_bytes);
    rnn_dynrouting_kernel<<<BTOT/64, 256, smem_bytes>>>(
        y0, noise, stim, rew, instr, WinRaw, Wrec, brec, wout, bout, out);
}